// round 16
// baseline (speedup 1.0000x reference)
#include <cuda_runtime.h>
#include <cuda_fp16.h>
#include <math_constants.h>
#include <cstdint>

#define Bq 4
#define Tq 1024
#define Cq 16
#define Dq 256
#define NHEADS (Bq*Cq)
#define MTOT (Bq*Tq*Cq)

// scale = (1/sqrt(256)) * log2(e); pre-applied to Q in the QKV epilogue
#define SCL2 0.09014195388f

__device__ __align__(128) __half g_xb[(size_t)MTOT * Dq];
__device__ __align__(128) __half g_wb[3 * Dq * Dq];
__device__ __align__(128) __half g_q [(size_t)NHEADS * Tq * Dq];
__device__ __align__(128) __half g_k [(size_t)NHEADS * Tq * Dq];
__device__ __align__(128) __half g_v [(size_t)NHEADS * Tq * Dq];
__device__ __align__(128) unsigned char g_mt[NHEADS * Tq];

static __device__ __forceinline__ unsigned packh(float a, float b) {
    __half2 h = __floats2half2_rn(a, b);
    return *reinterpret_cast<unsigned*>(&h);
}
static __device__ __forceinline__ float2 unph(unsigned u) {
    __half2 h = *reinterpret_cast<__half2*>(&u);
    return __half22float2(h);
}
static __device__ __forceinline__ unsigned hmul2u(unsigned a, unsigned b) {
    __half2 r = __hmul2(*reinterpret_cast<__half2*>(&a),
                        *reinterpret_cast<__half2*>(&b));
    return *reinterpret_cast<unsigned*>(&r);
}
static __device__ __forceinline__ void mma_f16_f16(
    unsigned& d0, unsigned& d1,
    unsigned a0, unsigned a1, unsigned a2, unsigned a3,
    unsigned b0, unsigned b1)
{
    asm volatile(
        "mma.sync.aligned.m16n8k16.row.col.f16.f16.f16.f16 "
        "{%0,%1}, {%2,%3,%4,%5}, {%6,%7}, {%0,%1};\n"
        : "+r"(d0), "+r"(d1)
        : "r"(a0), "r"(a1), "r"(a2), "r"(a3), "r"(b0), "r"(b1));
}
static __device__ __forceinline__ void ldsm_x4(
    unsigned& r0, unsigned& r1, unsigned& r2, unsigned& r3, unsigned addr)
{
    asm volatile("ldmatrix.sync.aligned.m8n8.x4.shared.b16 {%0,%1,%2,%3}, [%4];"
        : "=r"(r0), "=r"(r1), "=r"(r2), "=r"(r3) : "r"(addr));
}
static __device__ __forceinline__ void ldsm_x4_t(
    unsigned& r0, unsigned& r1, unsigned& r2, unsigned& r3, unsigned addr)
{
    asm volatile("ldmatrix.sync.aligned.m8n8.x4.trans.shared.b16 {%0,%1,%2,%3}, [%4];"
        : "=r"(r0), "=r"(r1), "=r"(r2), "=r"(r3) : "r"(addr));
}

#define CPA16(d, s) asm volatile("cp.async.cg.shared.global [%0], [%1], 16;" :: "r"(d), "l"(s))
#define CP_COMMIT() asm volatile("cp.async.commit_group;")
#define CP_WAIT(n)  asm volatile("cp.async.wait_group %0;" :: "n"(n))

// ---------------------------------------------------------------------------
__global__ void conv_x_kernel(const float* __restrict__ x)
{
    int i = blockIdx.x * blockDim.x + threadIdx.x;
    const float4 v = ((const float4*)x)[i];
    ((uint2*)g_xb)[i] = make_uint2(packh(v.x, v.y), packh(v.z, v.w));
}
__global__ void conv_w_kernel(const float* __restrict__ wq,
                              const float* __restrict__ wk,
                              const float* __restrict__ wv)
{
    int i = blockIdx.x * blockDim.x + threadIdx.x;
    g_wb[i]          = __float2half(wq[i]);
    g_wb[i + 65536]  = __float2half(wk[i]);
    g_wb[i + 131072] = __float2half(wv[i]);
}
__global__ void conv_m_kernel(const unsigned char* __restrict__ xmask)
{
    int i = blockIdx.x * blockDim.x + threadIdx.x;
    int h = i >> 10, t = i & 1023;
    int b = h >> 4,  c = h & 15;
    g_mt[i] = xmask[(size_t)((b << 10) + t) * Cq + c];
}

// ---------------------------------------------------------------------------
// QKV occ2 (R13/R15): CTA = 64M x 128N, 128 threads, K=256.
// Q output pre-scaled by SCL2 (commutes with RoPE rotation).
// ---------------------------------------------------------------------------
#define QW_OFF 0u
#define QX_OFF 67584u
#define QK2_SMEM (67584 + 33792)

__global__ __launch_bounds__(128, 2) void qkv_occ2_kernel(
    const int*   __restrict__ pos,
    const float* __restrict__ pe,
    const float* __restrict__ bq,
    const float* __restrict__ bk,
    const float* __restrict__ bv)
{
    extern __shared__ char sm[];
    const unsigned su = (unsigned)__cvta_generic_to_shared(sm);
    const int tid = threadIdx.x, w = tid >> 5, lane = tid & 31;
    const int q = lane & 3, lr = lane >> 2, g = lane >> 3, r8 = lane & 7;
    const int wm = w >> 1, wn = w & 1;
    const int mat = blockIdx.x >> 1;
    const int n0  = (blockIdx.x & 1) * 128;
    const int m0b = blockIdx.y * 128;

    const __half* wb = g_wb + mat * 65536 + n0 * Dq;
#pragma unroll
    for (int it = 0; it < 32; ++it) {
        int idx = it * 128 + tid;
        int row = idx >> 5, ch = idx & 31;
        CPA16(su + QW_OFF + (unsigned)(row * 528 + ch * 16), wb + row * Dq + ch * 8);
    }
    auto issue_x = [&](int mt) {
        const __half* src = g_xb + (size_t)(m0b + mt * 64) * Dq;
#pragma unroll
        for (int it = 0; it < 16; ++it) {
            int idx = it * 128 + tid;
            int row = idx >> 5, ch = idx & 31;
            CPA16(su + QX_OFF + (unsigned)(row * 528 + ch * 16), src + row * Dq + ch * 8);
        }
    };
    issue_x(0);
    CP_COMMIT();

    const float* bias = (mat == 0) ? bq : (mat == 1) ? bk : bv;
    __half* outp = (mat == 0) ? g_q : (mat == 1) ? g_k : g_v;
    const float oscale = (mat == 0) ? SCL2 : 1.0f;

    const unsigned a_base = su + QX_OFF +
        (unsigned)((wm * 32 + (g & 1) * 8 + r8) * 528 + ((g >> 1) * 8) * 2);
    const unsigned b_base = su + QW_OFF +
        (unsigned)((wn * 64 + (g >> 1) * 8 + r8) * 528 + ((g & 1) * 8) * 2);

#pragma unroll 1
    for (int mt = 0; mt < 2; ++mt) {
        CP_WAIT(0);
        __syncthreads();

        unsigned acc[2][8][2];
#pragma unroll
        for (int m2 = 0; m2 < 2; ++m2)
#pragma unroll
            for (int nt = 0; nt < 8; ++nt) { acc[m2][nt][0] = 0u; acc[m2][nt][1] = 0u; }

#pragma unroll
        for (int kk = 0; kk < 16; ++kk) {
            unsigned af[2][4];
#pragma unroll
            for (int m2 = 0; m2 < 2; ++m2)
                ldsm_x4(af[m2][0], af[m2][1], af[m2][2], af[m2][3],
                        a_base + (unsigned)(m2 * 16 * 528) + kk * 32);
#pragma unroll
            for (int nt = 0; nt < 4; ++nt) {
                unsigned b0, b1, b2, b3;
                ldsm_x4(b0, b1, b2, b3, b_base + (unsigned)(nt * 16 * 528) + kk * 32);
#pragma unroll
                for (int m2 = 0; m2 < 2; ++m2) {
                    mma_f16_f16(acc[m2][2*nt][0],   acc[m2][2*nt][1],
                                af[m2][0], af[m2][1], af[m2][2], af[m2][3], b0, b1);
                    mma_f16_f16(acc[m2][2*nt+1][0], acc[m2][2*nt+1][1],
                                af[m2][0], af[m2][1], af[m2][2], af[m2][3], b2, b3);
                }
            }
        }
        __syncthreads();
        if (mt == 0) { issue_x(1); }
        CP_COMMIT();

        const int m0 = m0b + mt * 64;
#pragma unroll
        for (int m2 = 0; m2 < 2; ++m2) {
            const int tokA = m0 + wm * 32 + m2 * 16 + lr;
            const int tokB = tokA + 8;
            const int bA = tokA >> 14, tA = (tokA >> 4) & (Tq-1), cA = tokA & (Cq-1);
            const int bB = tokB >> 14, tB = (tokB >> 4) & (Tq-1), cB = tokB & (Cq-1);
            __half* rowA = outp + ((size_t)(bA * Cq + cA) * Tq + tA) * Dq;
            __half* rowB = outp + ((size_t)(bB * Cq + cB) * Tq + tB) * Dq;
            int pA = 0, pB = 0;
            if (mat < 2) { pA = pos[tokA]; pB = pos[tokB]; }
#pragma unroll
            for (int nt = 0; nt < 8; ++nt) {
                const int col = n0 + wn * 64 + nt * 8 + 2 * q;
                const float2 b2 = *(const float2*)(bias + col);
                float2 va = unph(acc[m2][nt][0]);
                float2 vb = unph(acc[m2][nt][1]);
                float v0 = va.x + b2.x, v1 = va.y + b2.y;
                float v2 = vb.x + b2.x, v3 = vb.y + b2.y;
                if (mat < 2) {
                    const float2 csA = *(const float2*)(pe + (size_t)pA * Dq + col);
                    const float2 csB = *(const float2*)(pe + (size_t)pB * Dq + col);
                    float r0 = v0 * csA.x - v1 * csA.y;
                    v1 = v0 * csA.y + v1 * csA.x; v0 = r0;
                    float r2 = v2 * csB.x - v3 * csB.y;
                    v3 = v2 * csB.y + v3 * csB.x; v2 = r2;
                }
                *(unsigned*)&rowA[col] = packh(v0 * oscale, v1 * oscale);
                *(unsigned*)&rowB[col] = packh(v2 * oscale, v3 * oscale);
            }
        }
    }
}

// ---------------------------------------------------------------------------
// Flash attention (R15 structure): occ-2, 4 warps, 64 q-rows, K-tile 32,
// 3-stage ring, exp2f online softmax. Q pre-scaled, so S is already in the
// log2 domain -> masked select passes raw f16 values (no per-kt scale FMULs).
// ---------------------------------------------------------------------------
#define STR 264
#define KTILE 32
#define KB2 (KTILE * STR * 2)
#define STG (2 * KB2)
#define QM_OFF (3 * STG)
#define KM_OFF (QM_OFF + 64)
#define ATTN_SMEM (KM_OFF + 96 + 32)

__global__ __launch_bounds__(128, 2) void attn_occ2_kernel(
    const float* __restrict__ x,
    const float* __restrict__ lng,
    const float* __restrict__ lnb,
    const float* __restrict__ lsg,
    float* __restrict__ out)
{
    extern __shared__ char smraw[];
    const unsigned char* sQm  = (const unsigned char*)(smraw + QM_OFF);
    const unsigned char* sKmB = (const unsigned char*)(smraw + KM_OFF);
    const unsigned su = (unsigned)__cvta_generic_to_shared(smraw);

    const int tid  = threadIdx.x;
    const int w    = tid >> 5;
    const int lane = tid & 31;
    const int q    = lane & 3;
    const int lr   = lane >> 2;
    const int g    = lane >> 3;
    const int r8   = lane & 7;

    const int h  = blockIdx.y;
    const int b  = h >> 4, c = h & 15;
    const int q0 = blockIdx.x * 64;

    const __half* qg = g_q + ((size_t)h * Tq + q0) * Dq;
    const __half* kg = g_k + (size_t)h * Tq * Dq;
    const __half* vg = g_v + (size_t)h * Tq * Dq;
    const unsigned char* mg = g_mt + h * Tq;

#pragma unroll
    for (int it = 0; it < 16; ++it) {
        int idx = it * 128 + tid;
        int row = idx >> 5, cc = idx & 31;
        CPA16(su + (unsigned)(row * STR * 2 + cc * 16), qg + row * Dq + cc * 8);
    }
    if (tid < 4) CPA16(su + QM_OFF + tid * 16, mg + q0 + tid * 16);
    CP_COMMIT(); CP_WAIT(0);
    __syncthreads();

    unsigned qf[16][4];
    const unsigned qa = su +
        ((unsigned)(w * 16 + (g & 1) * 8 + r8) * STR + (g >> 1) * 8) * 2;
#pragma unroll
    for (int kk = 0; kk < 16; ++kk)
        ldsm_x4(qf[kk][0], qf[kk][1], qf[kk][2], qf[kk][3], qa + kk * 32);
    const int qmA = sQm[w * 16 + lr];
    const int qmB = sQm[w * 16 + lr + 8];
    __syncthreads();

    auto issue = [&](int kt) {
        const int st = kt % 3;
        const unsigned sb = su + st * STG;
        const int k0 = kt * KTILE;
#pragma unroll
        for (int it = 0; it < 8; ++it) {
            int idx = it * 128 + tid;
            int row = idx >> 5, cc = idx & 31;
            CPA16(sb + (unsigned)(row * STR * 2 + cc * 16),
                  kg + (size_t)(k0 + row) * Dq + cc * 8);
            CPA16(sb + KB2 + (unsigned)(row * STR * 2 + cc * 16),
                  vg + (size_t)(k0 + row) * Dq + cc * 8);
        }
        if (tid < 2) CPA16(su + KM_OFF + st * 32 + tid * 16, mg + k0 + tid * 16);
    };
    issue(0); CP_COMMIT();
    issue(1); CP_COMMIT();

    const unsigned koff = ((unsigned)((g >> 1) * 8 + r8) * STR + (g & 1) * 8) * 2;
    const unsigned voff = ((unsigned)((g & 1) * 8 + r8) * STR + (g >> 1) * 8) * 2;

    unsigned oacc[32][2];
#pragma unroll
    for (int j = 0; j < 32; ++j) { oacc[j][0] = 0u; oacc[j][1] = 0u; }
    float mrunA = -CUDART_INF_F, mrunB = -CUDART_INF_F;
    float lsumA = 0.f, lsumB = 0.f;

    for (int kt = 0; kt < 32; ++kt) {
        CP_WAIT(1);
        __syncthreads();
        if (kt + 2 < 32) { issue(kt + 2); }
        CP_COMMIT();

        const int st = kt % 3;
        const unsigned kb_s = su + st * STG;
        const unsigned vb_s = kb_s + KB2;
        const unsigned char* km = sKmB + st * 32;

        // ---- S = Q K^T (f16 accum; already log2-domain scaled) ----
        unsigned sacc[4][2];
#pragma unroll
        for (int nf = 0; nf < 4; ++nf) { sacc[nf][0] = 0u; sacc[nf][1] = 0u; }
#pragma unroll
        for (int kk = 0; kk < 16; ++kk) {
#pragma unroll
            for (int ng = 0; ng < 2; ++ng) {
                unsigned b0, b1, b2, b3;
                ldsm_x4(b0, b1, b2, b3,
                        kb_s + (unsigned)(ng * 16 * STR * 2) + kk * 32 + koff);
                mma_f16_f16(sacc[2*ng][0],   sacc[2*ng][1],
                            qf[kk][0], qf[kk][1], qf[kk][2], qf[kk][3], b0, b1);
                mma_f16_f16(sacc[2*ng+1][0], sacc[2*ng+1][1],
                            qf[kk][0], qf[kk][1], qf[kk][2], qf[kk][3], b2, b3);
            }
        }

        // ---- mask + row max (no scale op) ----
        float sv[4][4];
        float tmaxA = -CUDART_INF_F, tmaxB = -CUDART_INF_F;
#pragma unroll
        for (int nf = 0; nf < 4; ++nf) {
            const float2 lo = unph(sacc[nf][0]);
            const float2 hi = unph(sacc[nf][1]);
            const int cc = nf * 8 + 2 * q;
            const int k0m = km[cc], k1m = km[cc + 1];
            sv[nf][0] = (qmA | k0m) ? -CUDART_INF_F : lo.x;
            sv[nf][1] = (qmA | k1m) ? -CUDART_INF_F : lo.y;
            sv[nf][2] = (qmB | k0m) ? -CUDART_INF_F : hi.x;
            sv[nf][3] = (qmB | k1m) ? -CUDART_INF_F : hi.y;
            tmaxA = fmaxf(tmaxA, fmaxf(sv[nf][0], sv[nf][1]));
            tmaxB = fmaxf(tmaxB, fmaxf(sv[nf][2], sv[nf][3]));
        }
        tmaxA = fmaxf(tmaxA, __shfl_xor_sync(0xffffffffu, tmaxA, 1));
        tmaxA = fmaxf(tmaxA, __shfl_xor_sync(0xffffffffu, tmaxA, 2));
        tmaxB = fmaxf(tmaxB, __shfl_xor_sync(0xffffffffu, tmaxB, 1));
        tmaxB = fmaxf(tmaxB, __shfl_xor_sync(0xffffffffu, tmaxB, 2));

        const float mnA = fmaxf(mrunA, tmaxA);
        const float mnB = fmaxf(mrunB, tmaxB);
        const float corrA = (mnA == -CUDART_INF_F) ? 1.f : exp2f(mrunA - mnA);
        const float corrB = (mnB == -CUDART_INF_F) ? 1.f : exp2f(mrunB - mnB);
        const float mUA = (mnA == -CUDART_INF_F) ? 0.f : mnA;
        const float mUB = (mnB == -CUDART_INF_F) ? 0.f : mnB;
        lsumA *= corrA; lsumB *= corrB;
        mrunA = mnA; mrunB = mnB;

        unsigned pa[2][4];
#pragma unroll
        for (int kk = 0; kk < 2; ++kk) {
            float p00 = exp2f(sv[2*kk][0]   - mUA);
            float p01 = exp2f(sv[2*kk][1]   - mUA);
            float p02 = exp2f(sv[2*kk][2]   - mUB);
            float p03 = exp2f(sv[2*kk][3]   - mUB);
            float p10 = exp2f(sv[2*kk+1][0] - mUA);
            float p11 = exp2f(sv[2*kk+1][1] - mUA);
            float p12 = exp2f(sv[2*kk+1][2] - mUB);
            float p13 = exp2f(sv[2*kk+1][3] - mUB);
            lsumA += p00 + p01 + p10 + p11;
            lsumB += p02 + p03 + p12 + p13;
            pa[kk][0] = packh(p00, p01);
            pa[kk][1] = packh(p02, p03);
            pa[kk][2] = packh(p10, p11);
            pa[kk][3] = packh(p12, p13);
        }

        const unsigned cA2 = packh(corrA, corrA);
        const unsigned cB2 = packh(corrB, corrB);
#pragma unroll
        for (int j = 0; j < 32; ++j) {
            oacc[j][0] = hmul2u(oacc[j][0], cA2);
            oacc[j][1] = hmul2u(oacc[j][1], cB2);
        }

        // ---- O += P V ----
#pragma unroll
        for (int kk = 0; kk < 2; ++kk) {
#pragma unroll
            for (int dg = 0; dg < 16; ++dg) {
                unsigned v0, v1, v2, v3;
                ldsm_x4_t(v0, v1, v2, v3,
                          vb_s + (unsigned)(kk * 16 * STR * 2) + dg * 32 + voff);
                mma_f16_f16(oacc[2*dg][0],   oacc[2*dg][1],
                            pa[kk][0], pa[kk][1], pa[kk][2], pa[kk][3], v0, v1);
                mma_f16_f16(oacc[2*dg+1][0], oacc[2*dg+1][1],
                            pa[kk][0], pa[kk][1], pa[kk][2], pa[kk][3], v2, v3);
            }
        }
    }

    // ---- epilogue: residual + LayerScale + LayerNorm ----
    lsumA += __shfl_xor_sync(0xffffffffu, lsumA, 1);
    lsumA += __shfl_xor_sync(0xffffffffu, lsumA, 2);
    lsumB += __shfl_xor_sync(0xffffffffu, lsumB, 1);
    lsumB += __shfl_xor_sync(0xffffffffu, lsumB, 2);
    const float invA = (lsumA > 0.f) ? (1.f / lsumA) : 0.f;
    const float invB = (lsumB > 0.f) ? (1.f / lsumB) : 0.f;

    const int gtA = q0 + w * 16 + lr;
    const int gtB = gtA + 8;
    const size_t miA = (size_t)(b * Tq + gtA) * Cq + c;
    const size_t miB = (size_t)(b * Tq + gtB) * Cq + c;
    const float* xA = x + miA * Dq;
    const float* xB = x + miB * Dq;

    float yv[32][4];
    float sumA = 0.f, ssqA = 0.f, sumB = 0.f, ssqB = 0.f;
#pragma unroll
    for (int j = 0; j < 32; ++j) {
        const int cc = j * 8 + 2 * q;
        const float2 g2 = *(const float2*)(lsg + cc);
        const float2 xa = *(const float2*)(xA + cc);
        const float2 xb2 = *(const float2*)(xB + cc);
        const float2 oa = unph(oacc[j][0]);
        const float2 ob = unph(oacc[j][1]);
        float y0 = xa.x  + g2.x * (oa.x * invA);
        float y1 = xa.y  + g2.y * (oa.y * invA);
        float y2 = xb2.x + g2.x * (ob.x * invB);
        float y3 = xb2.y + g2.y * (ob.y * invB);
        yv[j][0] = y0; yv[j][1] = y1; yv[j][2] = y2; yv[j][3] = y3;
        sumA += y0 + y1;  ssqA += y0 * y0 + y1 * y1;
        sumB += y2 + y3;  ssqB += y2 * y2 + y3 * y3;
    }
    sumA += __shfl_xor_sync(0xffffffffu, sumA, 1);
    sumA += __shfl_xor_sync(0xffffffffu, sumA, 2);
    ssqA += __shfl_xor_sync(0xffffffffu, ssqA, 1);
    ssqA += __shfl_xor_sync(0xffffffffu, ssqA, 2);
    sumB += __shfl_xor_sync(0xffffffffu, sumB, 1);
    sumB += __shfl_xor_sync(0xffffffffu, sumB, 2);
    ssqB += __shfl_xor_sync(0xffffffffu, ssqB, 1);
    ssqB += __shfl_xor_sync(0xffffffffu, ssqB, 2);

    const float muA = sumA * (1.f / 256.f);
    const float muB = sumB * (1.f / 256.f);
    const float rsA = rsqrtf(ssqA * (1.f / 256.f) - muA * muA + 1e-5f);
    const float rsB = rsqrtf(ssqB * (1.f / 256.f) - muB * muB + 1e-5f);

    float* oA = out + miA * Dq;
    float* oB = out + miB * Dq;
#pragma unroll
    for (int j = 0; j < 32; ++j) {
        const int cc = j * 8 + 2 * q;
        const float2 gg = *(const float2*)(lng + cc);
        const float2 bb = *(const float2*)(lnb + cc);
        float2 r0, r1;
        r0.x = (yv[j][0] - muA) * rsA * gg.x + bb.x;
        r0.y = (yv[j][1] - muA) * rsA * gg.y + bb.y;
        r1.x = (yv[j][2] - muB) * rsB * gg.x + bb.x;
        r1.y = (yv[j][3] - muB) * rsB * gg.y + bb.y;
        *(float2*)(oA + cc) = r0;
        *(float2*)(oB + cc) = r1;
    }
}

// ---------------------------------------------------------------------------
extern "C" void kernel_launch(void* const* d_in, const int* in_sizes, int n_in,
                              void* d_out, int out_size)
{
    const float* x   = (const float*)d_in[0];
    const unsigned char* xmask = (const unsigned char*)d_in[1];
    const int*   pos = (const int*)d_in[2];
    const float* pe  = (const float*)d_in[3];
    const float* wq  = (const float*)d_in[4];
    const float* bq  = (const float*)d_in[5];
    const float* wk  = (const float*)d_in[6];
    const float* bk  = (const float*)d_in[7];
    const float* wv  = (const float*)d_in[8];
    const float* bv  = (const float*)d_in[9];
    const float* lng = (const float*)d_in[10];
    const float* lnb = (const float*)d_in[11];
    const float* lsg = (const float*)d_in[12];
    float* out = (float*)d_out;

    conv_x_kernel<<<(MTOT * Dq / 4) / 256, 256>>>(x);
    conv_w_kernel<<<(Dq * Dq) / 256, 256>>>(wq, wk, wv);
    conv_m_kernel<<<(NHEADS * Tq) / 256, 256>>>(xmask);

    cudaFuncSetAttribute(qkv_occ2_kernel,
                         cudaFuncAttributeMaxDynamicSharedMemorySize, QK2_SMEM);
    qkv_occ2_kernel<<<dim3(6, MTOT / 128), 128, QK2_SMEM>>>(pos, pe, bq, bk, bv);

    cudaFuncSetAttribute(attn_occ2_kernel,
                         cudaFuncAttributeMaxDynamicSharedMemorySize, ATTN_SMEM);
    attn_occ2_kernel<<<dim3(Tq / 64, NHEADS), 128, ATTN_SMEM>>>(
        x, lng, lnb, lsg, out);
}

// round 17
// speedup vs baseline: 1.0244x; 1.0244x over previous
#include <cuda_runtime.h>
#include <cuda_fp16.h>
#include <math_constants.h>
#include <cstdint>

#define Bq 4
#define Tq 1024
#define Cq 16
#define Dq 256
#define NHEADS (Bq*Cq)
#define MTOT (Bq*Tq*Cq)

// scale = (1/sqrt(256)) * log2(e), applied before exp2f
#define SCL2 0.09014195388f

__device__ __align__(128) __half g_xb[(size_t)MTOT * Dq];
__device__ __align__(128) __half g_wb[3 * Dq * Dq];
__device__ __align__(128) __half g_q [(size_t)NHEADS * Tq * Dq];
__device__ __align__(128) __half g_k [(size_t)NHEADS * Tq * Dq];
__device__ __align__(128) __half g_v [(size_t)NHEADS * Tq * Dq];
__device__ __align__(128) unsigned char g_mt[NHEADS * Tq];

static __device__ __forceinline__ unsigned packh(float a, float b) {
    __half2 h = __floats2half2_rn(a, b);
    return *reinterpret_cast<unsigned*>(&h);
}
static __device__ __forceinline__ float2 unph(unsigned u) {
    __half2 h = *reinterpret_cast<__half2*>(&u);
    return __half22float2(h);
}
static __device__ __forceinline__ unsigned hmul2u(unsigned a, unsigned b) {
    __half2 r = __hmul2(*reinterpret_cast<__half2*>(&a),
                        *reinterpret_cast<__half2*>(&b));
    return *reinterpret_cast<unsigned*>(&r);
}
static __device__ __forceinline__ void mma_f16_f16(
    unsigned& d0, unsigned& d1,
    unsigned a0, unsigned a1, unsigned a2, unsigned a3,
    unsigned b0, unsigned b1)
{
    asm volatile(
        "mma.sync.aligned.m16n8k16.row.col.f16.f16.f16.f16 "
        "{%0,%1}, {%2,%3,%4,%5}, {%6,%7}, {%0,%1};\n"
        : "+r"(d0), "+r"(d1)
        : "r"(a0), "r"(a1), "r"(a2), "r"(a3), "r"(b0), "r"(b1));
}
static __device__ __forceinline__ void ldsm_x4(
    unsigned& r0, unsigned& r1, unsigned& r2, unsigned& r3, unsigned addr)
{
    asm volatile("ldmatrix.sync.aligned.m8n8.x4.shared.b16 {%0,%1,%2,%3}, [%4];"
        : "=r"(r0), "=r"(r1), "=r"(r2), "=r"(r3) : "r"(addr));
}
static __device__ __forceinline__ void ldsm_x4_t(
    unsigned& r0, unsigned& r1, unsigned& r2, unsigned& r3, unsigned addr)
{
    asm volatile("ldmatrix.sync.aligned.m8n8.x4.trans.shared.b16 {%0,%1,%2,%3}, [%4];"
        : "=r"(r0), "=r"(r1), "=r"(r2), "=r"(r3) : "r"(addr));
}

#define CPA16(d, s) asm volatile("cp.async.cg.shared.global [%0], [%1], 16;" :: "r"(d), "l"(s))
#define CP_COMMIT() asm volatile("cp.async.commit_group;")
#define CP_WAIT(n)  asm volatile("cp.async.wait_group %0;" :: "n"(n))

// ---------------------------------------------------------------------------
// Fused converter: blocks [0,16384) convert x, [16384,16640) convert w,
// [16640,16704) build the head-major mask.
// ---------------------------------------------------------------------------
__global__ void conv_all_kernel(const float* __restrict__ x,
                                const float* __restrict__ wq,
                                const float* __restrict__ wk,
                                const float* __restrict__ wv,
                                const unsigned char* __restrict__ xmask)
{
    const int bx = blockIdx.x;
    if (bx < 16384) {
        int i = bx * 256 + threadIdx.x;                 // float4 index
        const float4 v = ((const float4*)x)[i];
        ((uint2*)g_xb)[i] = make_uint2(packh(v.x, v.y), packh(v.z, v.w));
    } else if (bx < 16640) {
        int i = (bx - 16384) * 256 + threadIdx.x;       // 0..65535
        g_wb[i]          = __float2half(wq[i]);
        g_wb[i + 65536]  = __float2half(wk[i]);
        g_wb[i + 131072] = __float2half(wv[i]);
    } else {
        int i = (bx - 16640) * 1024 + threadIdx.x * 4;  // 0..65532 step 4
#pragma unroll
        for (int j = 0; j < 4; ++j) {
            int idx = i + j;
            int h = idx >> 10, t = idx & 1023;
            int b = h >> 4,  c = h & 15;
            g_mt[idx] = xmask[(size_t)((b << 10) + t) * Cq + c];
        }
    }
}

// ---------------------------------------------------------------------------
// QKV occ2 (R13/R15, verified): CTA = 64M x 128N, 128 threads, K=256.
// ---------------------------------------------------------------------------
#define QW_OFF 0u
#define QX_OFF 67584u
#define QK2_SMEM (67584 + 33792)

__global__ __launch_bounds__(128, 2) void qkv_occ2_kernel(
    const int*   __restrict__ pos,
    const float* __restrict__ pe,
    const float* __restrict__ bq,
    const float* __restrict__ bk,
    const float* __restrict__ bv)
{
    extern __shared__ char sm[];
    const unsigned su = (unsigned)__cvta_generic_to_shared(sm);
    const int tid = threadIdx.x, w = tid >> 5, lane = tid & 31;
    const int q = lane & 3, lr = lane >> 2, g = lane >> 3, r8 = lane & 7;
    const int wm = w >> 1, wn = w & 1;
    const int mat = blockIdx.x >> 1;
    const int n0  = (blockIdx.x & 1) * 128;
    const int m0b = blockIdx.y * 128;

    const __half* wb = g_wb + mat * 65536 + n0 * Dq;
#pragma unroll
    for (int it = 0; it < 32; ++it) {
        int idx = it * 128 + tid;
        int row = idx >> 5, ch = idx & 31;
        CPA16(su + QW_OFF + (unsigned)(row * 528 + ch * 16), wb + row * Dq + ch * 8);
    }
    auto issue_x = [&](int mt) {
        const __half* src = g_xb + (size_t)(m0b + mt * 64) * Dq;
#pragma unroll
        for (int it = 0; it < 16; ++it) {
            int idx = it * 128 + tid;
            int row = idx >> 5, ch = idx & 31;
            CPA16(su + QX_OFF + (unsigned)(row * 528 + ch * 16), src + row * Dq + ch * 8);
        }
    };
    issue_x(0);
    CP_COMMIT();

    const float* bias = (mat == 0) ? bq : (mat == 1) ? bk : bv;
    __half* outp = (mat == 0) ? g_q : (mat == 1) ? g_k : g_v;

    const unsigned a_base = su + QX_OFF +
        (unsigned)((wm * 32 + (g & 1) * 8 + r8) * 528 + ((g >> 1) * 8) * 2);
    const unsigned b_base = su + QW_OFF +
        (unsigned)((wn * 64 + (g >> 1) * 8 + r8) * 528 + ((g & 1) * 8) * 2);

#pragma unroll 1
    for (int mt = 0; mt < 2; ++mt) {
        CP_WAIT(0);
        __syncthreads();

        unsigned acc[2][8][2];
#pragma unroll
        for (int m2 = 0; m2 < 2; ++m2)
#pragma unroll
            for (int nt = 0; nt < 8; ++nt) { acc[m2][nt][0] = 0u; acc[m2][nt][1] = 0u; }

#pragma unroll
        for (int kk = 0; kk < 16; ++kk) {
            unsigned af[2][4];
#pragma unroll
            for (int m2 = 0; m2 < 2; ++m2)
                ldsm_x4(af[m2][0], af[m2][1], af[m2][2], af[m2][3],
                        a_base + (unsigned)(m2 * 16 * 528) + kk * 32);
#pragma unroll
            for (int nt = 0; nt < 4; ++nt) {
                unsigned b0, b1, b2, b3;
                ldsm_x4(b0, b1, b2, b3, b_base + (unsigned)(nt * 16 * 528) + kk * 32);
#pragma unroll
                for (int m2 = 0; m2 < 2; ++m2) {
                    mma_f16_f16(acc[m2][2*nt][0],   acc[m2][2*nt][1],
                                af[m2][0], af[m2][1], af[m2][2], af[m2][3], b0, b1);
                    mma_f16_f16(acc[m2][2*nt+1][0], acc[m2][2*nt+1][1],
                                af[m2][0], af[m2][1], af[m2][2], af[m2][3], b2, b3);
                }
            }
        }
        __syncthreads();
        if (mt == 0) { issue_x(1); }
        CP_COMMIT();

        const int m0 = m0b + mt * 64;
#pragma unroll
        for (int m2 = 0; m2 < 2; ++m2) {
            const int tokA = m0 + wm * 32 + m2 * 16 + lr;
            const int tokB = tokA + 8;
            const int bA = tokA >> 14, tA = (tokA >> 4) & (Tq-1), cA = tokA & (Cq-1);
            const int bB = tokB >> 14, tB = (tokB >> 4) & (Tq-1), cB = tokB & (Cq-1);
            __half* rowA = outp + ((size_t)(bA * Cq + cA) * Tq + tA) * Dq;
            __half* rowB = outp + ((size_t)(bB * Cq + cB) * Tq + tB) * Dq;
            int pA = 0, pB = 0;
            if (mat < 2) { pA = pos[tokA]; pB = pos[tokB]; }
#pragma unroll
            for (int nt = 0; nt < 8; ++nt) {
                const int col = n0 + wn * 64 + nt * 8 + 2 * q;
                const float2 b2 = *(const float2*)(bias + col);
                float2 va = unph(acc[m2][nt][0]);
                float2 vb = unph(acc[m2][nt][1]);
                float v0 = va.x + b2.x, v1 = va.y + b2.y;
                float v2 = vb.x + b2.x, v3 = vb.y + b2.y;
                if (mat < 2) {
                    const float2 csA = *(const float2*)(pe + (size_t)pA * Dq + col);
                    const float2 csB = *(const float2*)(pe + (size_t)pB * Dq + col);
                    float r0 = v0 * csA.x - v1 * csA.y;
                    v1 = v0 * csA.y + v1 * csA.x; v0 = r0;
                    float r2 = v2 * csB.x - v3 * csB.y;
                    v3 = v2 * csB.y + v3 * csB.x; v2 = r2;
                }
                *(unsigned*)&rowA[col] = packh(v0, v1);
                *(unsigned*)&rowB[col] = packh(v2, v3);
            }
        }
    }
}

// ---------------------------------------------------------------------------
// Flash attention (R15, verified best): occ-2, 4 warps, 64 q-rows, K-tile 32,
// 3-stage ring, exp2f online softmax (log2-domain scale folded into SCL2).
// ---------------------------------------------------------------------------
#define STR 264
#define KTILE 32
#define KB2 (KTILE * STR * 2)
#define STG (2 * KB2)
#define QM_OFF (3 * STG)
#define KM_OFF (QM_OFF + 64)
#define ATTN_SMEM (KM_OFF + 96 + 32)

__global__ __launch_bounds__(128, 2) void attn_occ2_kernel(
    const float* __restrict__ x,
    const float* __restrict__ lng,
    const float* __restrict__ lnb,
    const float* __restrict__ lsg,
    float* __restrict__ out)
{
    extern __shared__ char smraw[];
    const unsigned char* sQm  = (const unsigned char*)(smraw + QM_OFF);
    const unsigned char* sKmB = (const unsigned char*)(smraw + KM_OFF);
    const unsigned su = (unsigned)__cvta_generic_to_shared(smraw);

    const int tid  = threadIdx.x;
    const int w    = tid >> 5;
    const int lane = tid & 31;
    const int q    = lane & 3;
    const int lr   = lane >> 2;
    const int g    = lane >> 3;
    const int r8   = lane & 7;

    const int h  = blockIdx.y;
    const int b  = h >> 4, c = h & 15;
    const int q0 = blockIdx.x * 64;

    const __half* qg = g_q + ((size_t)h * Tq + q0) * Dq;
    const __half* kg = g_k + (size_t)h * Tq * Dq;
    const __half* vg = g_v + (size_t)h * Tq * Dq;
    const unsigned char* mg = g_mt + h * Tq;

#pragma unroll
    for (int it = 0; it < 16; ++it) {
        int idx = it * 128 + tid;
        int row = idx >> 5, cc = idx & 31;
        CPA16(su + (unsigned)(row * STR * 2 + cc * 16), qg + row * Dq + cc * 8);
    }
    if (tid < 4) CPA16(su + QM_OFF + tid * 16, mg + q0 + tid * 16);
    CP_COMMIT(); CP_WAIT(0);
    __syncthreads();

    unsigned qf[16][4];
    const unsigned qa = su +
        ((unsigned)(w * 16 + (g & 1) * 8 + r8) * STR + (g >> 1) * 8) * 2;
#pragma unroll
    for (int kk = 0; kk < 16; ++kk)
        ldsm_x4(qf[kk][0], qf[kk][1], qf[kk][2], qf[kk][3], qa + kk * 32);
    const int qmA = sQm[w * 16 + lr];
    const int qmB = sQm[w * 16 + lr + 8];
    __syncthreads();

    auto issue = [&](int kt) {
        const int st = kt % 3;
        const unsigned sb = su + st * STG;
        const int k0 = kt * KTILE;
#pragma unroll
        for (int it = 0; it < 8; ++it) {
            int idx = it * 128 + tid;
            int row = idx >> 5, cc = idx & 31;
            CPA16(sb + (unsigned)(row * STR * 2 + cc * 16),
                  kg + (size_t)(k0 + row) * Dq + cc * 8);
            CPA16(sb + KB2 + (unsigned)(row * STR * 2 + cc * 16),
                  vg + (size_t)(k0 + row) * Dq + cc * 8);
        }
        if (tid < 2) CPA16(su + KM_OFF + st * 32 + tid * 16, mg + k0 + tid * 16);
    };
    issue(0); CP_COMMIT();
    issue(1); CP_COMMIT();

    const unsigned koff = ((unsigned)((g >> 1) * 8 + r8) * STR + (g & 1) * 8) * 2;
    const unsigned voff = ((unsigned)((g & 1) * 8 + r8) * STR + (g >> 1) * 8) * 2;

    unsigned oacc[32][2];
#pragma unroll
    for (int j = 0; j < 32; ++j) { oacc[j][0] = 0u; oacc[j][1] = 0u; }
    float mrunA = -CUDART_INF_F, mrunB = -CUDART_INF_F;
    float lsumA = 0.f, lsumB = 0.f;

    for (int kt = 0; kt < 32; ++kt) {
        CP_WAIT(1);
        __syncthreads();
        if (kt + 2 < 32) { issue(kt + 2); }
        CP_COMMIT();

        const int st = kt % 3;
        const unsigned kb_s = su + st * STG;
        const unsigned vb_s = kb_s + KB2;
        const unsigned char* km = sKmB + st * 32;

        // ---- S = Q K^T (f16 accum) ----
        unsigned sacc[4][2];
#pragma unroll
        for (int nf = 0; nf < 4; ++nf) { sacc[nf][0] = 0u; sacc[nf][1] = 0u; }
#pragma unroll
        for (int kk = 0; kk < 16; ++kk) {
#pragma unroll
            for (int ng = 0; ng < 2; ++ng) {
                unsigned b0, b1, b2, b3;
                ldsm_x4(b0, b1, b2, b3,
                        kb_s + (unsigned)(ng * 16 * STR * 2) + kk * 32 + koff);
                mma_f16_f16(sacc[2*ng][0],   sacc[2*ng][1],
                            qf[kk][0], qf[kk][1], qf[kk][2], qf[kk][3], b0, b1);
                mma_f16_f16(sacc[2*ng+1][0], sacc[2*ng+1][1],
                            qf[kk][0], qf[kk][1], qf[kk][2], qf[kk][3], b2, b3);
            }
        }

        // ---- mask + scale (log2 domain) + row max ----
        float sv[4][4];
        float tmaxA = -CUDART_INF_F, tmaxB = -CUDART_INF_F;
#pragma unroll
        for (int nf = 0; nf < 4; ++nf) {
            const float2 lo = unph(sacc[nf][0]);
            const float2 hi = unph(sacc[nf][1]);
            const int cc = nf * 8 + 2 * q;
            const int k0m = km[cc], k1m = km[cc + 1];
            sv[nf][0] = (qmA | k0m) ? -CUDART_INF_F : lo.x * SCL2;
            sv[nf][1] = (qmA | k1m) ? -CUDART_INF_F : lo.y * SCL2;
            sv[nf][2] = (qmB | k0m) ? -CUDART_INF_F : hi.x * SCL2;
            sv[nf][3] = (qmB | k1m) ? -CUDART_INF_F : hi.y * SCL2;
            tmaxA = fmaxf(tmaxA, fmaxf(sv[nf][0], sv[nf][1]));
            tmaxB = fmaxf(tmaxB, fmaxf(sv[nf][2], sv[nf][3]));
        }
        tmaxA = fmaxf(tmaxA, __shfl_xor_sync(0xffffffffu, tmaxA, 1));
        tmaxA = fmaxf(tmaxA, __shfl_xor_sync(0xffffffffu, tmaxA, 2));
        tmaxB = fmaxf(tmaxB, __shfl_xor_sync(0xffffffffu, tmaxB, 1));
        tmaxB = fmaxf(tmaxB, __shfl_xor_sync(0xffffffffu, tmaxB, 2));

        const float mnA = fmaxf(mrunA, tmaxA);
        const float mnB = fmaxf(mrunB, tmaxB);
        const float corrA = (mnA == -CUDART_INF_F) ? 1.f : exp2f(mrunA - mnA);
        const float corrB = (mnB == -CUDART_INF_F) ? 1.f : exp2f(mrunB - mnB);
        const float mUA = (mnA == -CUDART_INF_F) ? 0.f : mnA;
        const float mUB = (mnB == -CUDART_INF_F) ? 0.f : mnB;
        lsumA *= corrA; lsumB *= corrB;
        mrunA = mnA; mrunB = mnB;

        unsigned pa[2][4];
#pragma unroll
        for (int kk = 0; kk < 2; ++kk) {
            float p00 = exp2f(sv[2*kk][0]   - mUA);
            float p01 = exp2f(sv[2*kk][1]   - mUA);
            float p02 = exp2f(sv[2*kk][2]   - mUB);
            float p03 = exp2f(sv[2*kk][3]   - mUB);
            float p10 = exp2f(sv[2*kk+1][0] - mUA);
            float p11 = exp2f(sv[2*kk+1][1] - mUA);
            float p12 = exp2f(sv[2*kk+1][2] - mUB);
            float p13 = exp2f(sv[2*kk+1][3] - mUB);
            lsumA += p00 + p01 + p10 + p11;
            lsumB += p02 + p03 + p12 + p13;
            pa[kk][0] = packh(p00, p01);
            pa[kk][1] = packh(p02, p03);
            pa[kk][2] = packh(p10, p11);
            pa[kk][3] = packh(p12, p13);
        }

        const unsigned cA2 = packh(corrA, corrA);
        const unsigned cB2 = packh(corrB, corrB);
#pragma unroll
        for (int j = 0; j < 32; ++j) {
            oacc[j][0] = hmul2u(oacc[j][0], cA2);
            oacc[j][1] = hmul2u(oacc[j][1], cB2);
        }

        // ---- O += P V ----
#pragma unroll
        for (int kk = 0; kk < 2; ++kk) {
#pragma unroll
            for (int dg = 0; dg < 16; ++dg) {
                unsigned v0, v1, v2, v3;
                ldsm_x4_t(v0, v1, v2, v3,
                          vb_s + (unsigned)(kk * 16 * STR * 2) + dg * 32 + voff);
                mma_f16_f16(oacc[2*dg][0],   oacc[2*dg][1],
                            pa[kk][0], pa[kk][1], pa[kk][2], pa[kk][3], v0, v1);
                mma_f16_f16(oacc[2*dg+1][0], oacc[2*dg+1][1],
                            pa[kk][0], pa[kk][1], pa[kk][2], pa[kk][3], v2, v3);
            }
        }
    }

    // ---- epilogue: residual + LayerScale + LayerNorm ----
    lsumA += __shfl_xor_sync(0xffffffffu, lsumA, 1);
    lsumA += __shfl_xor_sync(0xffffffffu, lsumA, 2);
    lsumB += __shfl_xor_sync(0xffffffffu, lsumB, 1);
    lsumB += __shfl_xor_sync(0xffffffffu, lsumB, 2);
    const float invA = (lsumA > 0.f) ? (1.f / lsumA) : 0.f;
    const float invB = (lsumB > 0.f) ? (1.f / lsumB) : 0.f;

    const int gtA = q0 + w * 16 + lr;
    const int gtB = gtA + 8;
    const size_t miA = (size_t)(b * Tq + gtA) * Cq + c;
    const size_t miB = (size_t)(b * Tq + gtB) * Cq + c;
    const float* xA = x + miA * Dq;
    const float* xB = x + miB * Dq;

    float yv[32][4];
    float sumA = 0.f, ssqA = 0.f, sumB = 0.f, ssqB = 0.f;
#pragma unroll
    for (int j = 0; j < 32; ++j) {
        const int cc = j * 8 + 2 * q;
        const float2 g2 = *(const float2*)(lsg + cc);
        const float2 xa = *(const float2*)(xA + cc);
        const float2 xb2 = *(const float2*)(xB + cc);
        const float2 oa = unph(oacc[j][0]);
        const float2 ob = unph(oacc[j][1]);
        float y0 = xa.x  + g2.x * (oa.x * invA);
        float y1 = xa.y  + g2.y * (oa.y * invA);
        float y2 = xb2.x + g2.x * (ob.x * invB);
        float y3 = xb2.y + g2.y * (ob.y * invB);
        yv[j][0] = y0; yv[j][1] = y1; yv[j][2] = y2; yv[j][3] = y3;
        sumA += y0 + y1;  ssqA += y0 * y0 + y1 * y1;
        sumB += y2 + y3;  ssqB += y2 * y2 + y3 * y3;
    }
    sumA += __shfl_xor_sync(0xffffffffu, sumA, 1);
    sumA += __shfl_xor_sync(0xffffffffu, sumA, 2);
    ssqA += __shfl_xor_sync(0xffffffffu, ssqA, 1);
    ssqA += __shfl_xor_sync(0xffffffffu, ssqA, 2);
    sumB += __shfl_xor_sync(0xffffffffu, sumB, 1);
    sumB += __shfl_xor_sync(0xffffffffu, sumB, 2);
    ssqB += __shfl_xor_sync(0xffffffffu, ssqB, 1);
    ssqB += __shfl_xor_sync(0xffffffffu, ssqB, 2);

    const float muA = sumA * (1.f / 256.f);
    const float muB = sumB * (1.f / 256.f);
    const float rsA = rsqrtf(ssqA * (1.f / 256.f) - muA * muA + 1e-5f);
    const float rsB = rsqrtf(ssqB * (1.f / 256.f) - muB * muB + 1e-5f);

    float* oA = out + miA * Dq;
    float* oB = out + miB * Dq;
#pragma unroll
    for (int j = 0; j < 32; ++j) {
        const int cc = j * 8 + 2 * q;
        const float2 gg = *(const float2*)(lng + cc);
        const float2 bb = *(const float2*)(lnb + cc);
        float2 r0, r1;
        r0.x = (yv[j][0] - muA) * rsA * gg.x + bb.x;
        r0.y = (yv[j][1] - muA) * rsA * gg.y + bb.y;
        r1.x = (yv[j][2] - muB) * rsB * gg.x + bb.x;
        r1.y = (yv[j][3] - muB) * rsB * gg.y + bb.y;
        *(float2*)(oA + cc) = r0;
        *(float2*)(oB + cc) = r1;
    }
}

// ---------------------------------------------------------------------------
extern "C" void kernel_launch(void* const* d_in, const int* in_sizes, int n_in,
                              void* d_out, int out_size)
{
    const float* x   = (const float*)d_in[0];
    const unsigned char* xmask = (const unsigned char*)d_in[1];
    const int*   pos = (const int*)d_in[2];
    const float* pe  = (const float*)d_in[3];
    const float* wq  = (const float*)d_in[4];
    const float* bq  = (const float*)d_in[5];
    const float* wk  = (const float*)d_in[6];
    const float* bk  = (const float*)d_in[7];
    const float* wv  = (const float*)d_in[8];
    const float* bv  = (const float*)d_in[9];
    const float* lng = (const float*)d_in[10];
    const float* lnb = (const float*)d_in[11];
    const float* lsg = (const float*)d_in[12];
    float* out = (float*)d_out;

    conv_all_kernel<<<16704, 256>>>(x, wq, wk, wv, xmask);

    cudaFuncSetAttribute(qkv_occ2_kernel,
                         cudaFuncAttributeMaxDynamicSharedMemorySize, QK2_SMEM);
    qkv_occ2_kernel<<<dim3(6, MTOT / 128), 128, QK2_SMEM>>>(pos, pe, bq, bk, bv);

    cudaFuncSetAttribute(attn_occ2_kernel,
                         cudaFuncAttributeMaxDynamicSharedMemorySize, ATTN_SMEM);
    attn_occ2_kernel<<<dim3(Tq / 64, NHEADS), 128, ATTN_SMEM>>>(
        x, lng, lnb, lsg, out);
}